// round 1
// baseline (speedup 1.0000x reference)
#include <cuda_runtime.h>
#include <cuda_bf16.h>
#include <math.h>

// Inputs (metadata order): Xemb [8192,128] f32, scores [8192] f32 (unused),
// h_bias scalar f32, labels [8192] i32 (unused), pos_idx [P,2] i32, neg_idx [P,2] i32.
// Output: 2 floats {pos_loss, neg_loss}.

#define NUM_BLOCKS 1184   // 148 SMs * 8
#define THREADS    256    // 8 warps/block

__device__ float2 g_partials[NUM_BLOCKS];

__global__ __launch_bounds__(THREADS, 4)
void pair_loss_kernel(const float* __restrict__ X,
                      const float* __restrict__ h_bias,
                      const int2* __restrict__ pos_idx,
                      const int2* __restrict__ neg_idx,
                      int P)
{
    const int lane  = threadIdx.x & 31;
    const int warp  = threadIdx.x >> 5;
    const int gwarp = (blockIdx.x * blockDim.x + threadIdx.x) >> 5;
    const int nwarp = (gridDim.x * blockDim.x) >> 5;

    const float bias = log1pf(expf(*h_bias));  // softplus

    float pos_acc = 0.0f;
    float neg_acc = 0.0f;

    const long total = 2L * P;
    for (long t = gwarp; t < total; t += nwarp) {
        const bool is_pos = (t < P);
        const int2 idx = is_pos ? __ldg(&pos_idx[t]) : __ldg(&neg_idx[t - P]);

        const float4 a = __ldg(((const float4*)(X + (size_t)idx.x * 128)) + lane);
        const float4 b = __ldg(((const float4*)(X + (size_t)idx.y * 128)) + lane);

        const float dx = a.x - b.x;
        const float dy = a.y - b.y;
        const float dz = a.z - b.z;
        const float dw = a.w - b.w;
        float s = dx * dx + dy * dy + dz * dz + dw * dw;

        #pragma unroll
        for (int o = 16; o > 0; o >>= 1)
            s += __shfl_xor_sync(0xFFFFFFFFu, s, o);

        if (is_pos) {
            pos_acc += s;
        } else {
            const float d = sqrtf(s);
            const float r = fmaxf(bias - d, 0.0f);
            neg_acc += r * r;
        }
    }

    // Block reduce: lane 0 of each warp -> smem -> warp 0 reduces.
    __shared__ float s_pos[THREADS / 32];
    __shared__ float s_neg[THREADS / 32];
    if (lane == 0) {
        s_pos[warp] = pos_acc;
        s_neg[warp] = neg_acc;
    }
    __syncthreads();

    if (warp == 0) {
        float p = (lane < THREADS / 32) ? s_pos[lane] : 0.0f;
        float n = (lane < THREADS / 32) ? s_neg[lane] : 0.0f;
        #pragma unroll
        for (int o = 4; o > 0; o >>= 1) {
            p += __shfl_xor_sync(0xFFFFFFFFu, p, o);
            n += __shfl_xor_sync(0xFFFFFFFFu, n, o);
        }
        if (lane == 0)
            g_partials[blockIdx.x] = make_float2(p, n);
    }
}

__global__ void final_reduce_kernel(int nblocks, int P, float* __restrict__ out)
{
    const int lane = threadIdx.x & 31;
    const int warp = threadIdx.x >> 5;

    double ps = 0.0, ns = 0.0;
    for (int i = threadIdx.x; i < nblocks; i += blockDim.x) {
        float2 v = g_partials[i];
        ps += (double)v.x;
        ns += (double)v.y;
    }

    #pragma unroll
    for (int o = 16; o > 0; o >>= 1) {
        ps += __shfl_xor_sync(0xFFFFFFFFu, ps, o);
        ns += __shfl_xor_sync(0xFFFFFFFFu, ns, o);
    }

    __shared__ double sp[8], sn[8];
    if (lane == 0) { sp[warp] = ps; sn[warp] = ns; }
    __syncthreads();

    if (threadIdx.x == 0) {
        double tp = 0.0, tn = 0.0;
        for (int w = 0; w < (int)(blockDim.x >> 5); w++) { tp += sp[w]; tn += sn[w]; }
        out[0] = (float)(0.5 * tp / (double)P);
        out[1] = (float)(0.5 * tn / (double)P);
    }
}

extern "C" void kernel_launch(void* const* d_in, const int* in_sizes, int n_in,
                              void* d_out, int out_size)
{
    const float* X      = (const float*)d_in[0];
    const float* h_bias = (const float*)d_in[2];
    const int2*  pos    = (const int2*)d_in[4];
    const int2*  neg    = (const int2*)d_in[5];
    const int P = in_sizes[4] / 2;

    pair_loss_kernel<<<NUM_BLOCKS, THREADS>>>(X, h_bias, pos, neg, P);
    final_reduce_kernel<<<1, 256>>>(NUM_BLOCKS, P, (float*)d_out);
}